// round 16
// baseline (speedup 1.0000x reference)
#include <cuda_runtime.h>
#include <cuda_bf16.h>
#include <cstddef>
#include <cstdint>

#define NN 50000
#define EE 1600000
#define GG 256
#define EPSV 1e-5f

typedef unsigned long long u64;

// ---------------- ptx helpers ----------------
__device__ __forceinline__ u64 pack2(float lo, float hi) {
    u64 r;
    asm("mov.b64 %0, {%1, %2};" : "=l"(r) : "f"(lo), "f"(hi));
    return r;
}
__device__ __forceinline__ void unpack2(u64 v, float& lo, float& hi) {
    asm("mov.b64 {%0, %1}, %2;" : "=f"(lo), "=f"(hi) : "l"(v));
}
__device__ __forceinline__ void ffma2(u64& d, u64 a, u64 b) {
    asm("fma.rn.f32x2 %0, %1, %2, %0;" : "+l"(d) : "l"(a), "l"(b));
}
__device__ __forceinline__ uint32_t to_tf32(float f) {
    uint32_t u;
    asm("cvt.rna.tf32.f32 %0, %1;" : "=r"(u) : "f"(f));
    return u;
}
__device__ __forceinline__ void mma_tf32(float* c, const uint32_t* a, const uint32_t* b) {
    asm volatile(
        "mma.sync.aligned.m16n8k8.row.col.f32.tf32.tf32.f32 "
        "{%0,%1,%2,%3}, {%4,%5,%6,%7}, {%8,%9}, {%0,%1,%2,%3};"
        : "+f"(c[0]), "+f"(c[1]), "+f"(c[2]), "+f"(c[3])
        : "r"(a[0]), "r"(a[1]), "r"(a[2]), "r"(a[3]), "r"(b[0]), "r"(b[1]));
}
__device__ __forceinline__ void red2(float* addr, float a, float b) {
    asm volatile("red.global.add.v2.f32 [%0], {%1, %2};" :: "l"(addr), "f"(a), "f"(b) : "memory");
}

// ---------------- device scratch ----------------
__device__ __align__(16) float g_xbn[NN * 48];            // PRE-ROUNDED to tf32 (lossless: all consumers re-cvt)
__device__ __align__(16) __nv_bfloat16 g_bufA[(size_t)EE * 128];  // h1 -> h2 (bf16)
__device__ __align__(16) float g_h3[50048 * 128];
__device__ __align__(16) float g_agg[NN * 128];
__device__ __align__(16) float g_usum[GG * 128];
__device__ __align__(16) float g_hg[GG * 128];
// W frag regions (u32): eW1@0(12ks) eW2@12288(16) n1W1@28672(22) n1W2@51200(16) n2W1@67584(22) n2W2@90112(16)
__device__ __align__(16) uint32_t g_wfrag[106496];
__device__ int   g_colcnt[NN];
__device__ int   g_gcnt[GG];
// stats: x@0(48+48), e@96(128+128), n1@352, n2@608, gl@864
__device__ float g_stat[1120];
// scale/shift: x sc@0 sh@48 ; e sc@96 sh@224 ; n1 sc@352 sh@480 ; n2 sc@608 sh@736 ; gl sc@864 sh@992
__device__ float g_ss[1120];

__device__ __forceinline__ int clampi(int v, int hi) {
    return v < 0 ? 0 : (v >= hi ? hi - 1 : v);
}

// A-fragment u32 index within one 128-row tile
__device__ __forceinline__ int a2idx(int KS, int r, int ks, int kk) {
    return ((((r >> 4) * KS + ks) * 32 + (r & 7) * 4 + (kk & 3)) << 2) +
           (((kk & 4) >> 1) | ((r >> 3) & 1));
}

// ---------------- small kernels ----------------
__global__ void zero_k() {
    size_t i = (size_t)blockIdx.x * blockDim.x + threadIdx.x;
    size_t st = (size_t)gridDim.x * blockDim.x;
    for (size_t j = i; j < (size_t)NN * 128; j += st) g_agg[j] = 0.f;
    for (size_t j = i; j < NN; j += st) g_colcnt[j] = 0;
    for (size_t j = i; j < (size_t)GG * 128; j += st) g_usum[j] = 0.f;
    for (size_t j = i; j < GG; j += st) g_gcnt[j] = 0;
    for (size_t j = i; j < 1120; j += st) g_stat[j] = 0.f;
}

__global__ void xstats_k(const float* __restrict__ x) {
    __shared__ float ss[48], sq[48];
    int t = threadIdx.x;
    if (t < 48) { ss[t] = 0.f; sq[t] = 0.f; }
    __syncthreads();
    long long st = (long long)gridDim.x * blockDim.x;
    for (long long i = (long long)blockIdx.x * blockDim.x + t; i < (long long)NN * 48; i += st) {
        float v = x[i];
        int c = (int)(i % 48);
        atomicAdd(&ss[c], v);
        atomicAdd(&sq[c], v * v);
    }
    __syncthreads();
    if (t < 48) {
        atomicAdd(&g_stat[t], ss[t]);
        atomicAdd(&g_stat[48 + t], sq[t]);
    }
}

__global__ void finalize_k(const float* __restrict__ gamma, const float* __restrict__ beta,
                           int stat_off, int sc_off, int sh_off, int C, float cnt) {
    int c = threadIdx.x;
    if (c < C) {
        float m = g_stat[stat_off + c] / cnt;
        float v = g_stat[stat_off + C + c] / cnt - m * m;
        float s = gamma[c] * rsqrtf(v + EPSV);
        g_ss[sc_off + c] = s;
        g_ss[sh_off + c] = beta[c] - m * s;
    }
}

// store pre-rounded to tf32: all consumers cvt to tf32 before mma, so this is lossless
__global__ void xbn_k(const float* __restrict__ x) {
    long long st = (long long)gridDim.x * blockDim.x;
    for (long long i = (long long)blockIdx.x * blockDim.x + threadIdx.x; i < (long long)NN * 48; i += st) {
        int c = (int)(i % 48);
        g_xbn[i] = __uint_as_float(to_tf32(x[i] * g_ss[c] + g_ss[48 + c]));
    }
}

__global__ void count_k(const int* __restrict__ col, const int* __restrict__ batch) {
    long long st = (long long)gridDim.x * blockDim.x;
    for (long long i = (long long)blockIdx.x * blockDim.x + threadIdx.x; i < EE; i += st)
        atomicAdd(&g_colcnt[clampi(col[i], NN)], 1);
    for (long long i = (long long)blockIdx.x * blockDim.x + threadIdx.x; i < NN; i += st)
        atomicAdd(&g_gcnt[clampi(batch[i], GG)], 1);
}

__device__ __forceinline__ void prep_region(const float* W, int kact, int woff) {
    int stride = gridDim.x * blockDim.x;
    for (int idx = blockIdx.x * blockDim.x + threadIdx.x; idx < kact * 128; idx += stride) {
        int k = idx >> 7, n = idx & 127;
        int ks = k >> 3, kk = k & 7;
        int lane = (kk & 3) + (n & 7) * 4;
        int reg = (kk >= 4) ? 1 : 0;
        g_wfrag[woff + ((ks * 16 + (n >> 3)) * 32 + lane) * 2 + reg] = to_tf32(W[idx]);
    }
}
__global__ void prep_all(const float* __restrict__ eW1, const float* __restrict__ eW2,
                         const float* __restrict__ n1W1, const float* __restrict__ n1W2,
                         const float* __restrict__ n2W1, const float* __restrict__ n2W2) {
    prep_region(eW1, 96, 0);
    prep_region(eW2, 128, 12288);
    prep_region(n1W1, 176, 28672);
    prep_region(n1W2, 128, 51200);
    prep_region(n2W1, 176, 67584);
    prep_region(n2W2, 128, 90112);
}

// load 8 bf16 and expand to floats
__device__ __forceinline__ void ld_bf16x8(const __nv_bfloat16* src, float* f) {
    uint4 raw = *(const uint4*)src;
    float2 t;
    t = __bfloat1622float2(*(__nv_bfloat162*)&raw.x); f[0] = t.x; f[1] = t.y;
    t = __bfloat1622float2(*(__nv_bfloat162*)&raw.y); f[2] = t.x; f[3] = t.y;
    t = __bfloat1622float2(*(__nv_bfloat162*)&raw.z); f[4] = t.x; f[5] = t.y;
    t = __bfloat1622float2(*(__nv_bfloat162*)&raw.w); f[6] = t.x; f[7] = t.y;
}

// ---------------- mma.sync edge kernels (256 threads, 8 warps: 2M x 4N) ----------------

__global__ void __launch_bounds__(256, 2)
gemm_e1(const float* __restrict__ bias, const int* __restrict__ i0,
        const int* __restrict__ i1) {
    constexpr int KS = 12;
    extern __shared__ __align__(16) uint32_t A2[];
    __shared__ float xcs[128], xcq[128];
    __shared__ int sI0[128], sI1[128];
    __shared__ float sB[128];

    int tid = threadIdx.x;
    int lane = tid & 31, w = tid >> 5;
    int wm = w >> 2, wn = w & 3;
    int rbase = blockIdx.x * 128;

    if (tid < 128) {
        xcs[tid] = 0.f;
        xcq[tid] = 0.f;
        sB[tid] = bias[tid];
        sI0[tid] = clampi(i0[rbase + tid], NN);
        sI1[tid] = clampi(i1[rbase + tid], NN);
    }
    __syncthreads();

    // xbn pre-rounded to tf32: pure copy, no cvt
#pragma unroll
    for (int it = 0; it < 12; it++) {
        int v = tid + it * 256;
        int r = v / 24, q = v % 24;
        const float* src = (q < 12) ? (g_xbn + (size_t)sI0[r] * 48 + q * 4)
                                    : (g_xbn + (size_t)sI1[r] * 48 + (q - 12) * 4);
        float4 val = *(const float4*)src;
        int base = a2idx(KS, r, q >> 1, (q & 1) * 4);
        A2[base + 0] = __float_as_uint(val.x);
        A2[base + 4] = __float_as_uint(val.y);
        A2[base + 8] = __float_as_uint(val.z);
        A2[base + 12] = __float_as_uint(val.w);
    }
    __syncthreads();

    float acc[4][4][4];
#pragma unroll
    for (int mt = 0; mt < 4; mt++)
#pragma unroll
        for (int nt = 0; nt < 4; nt++)
#pragma unroll
            for (int e = 0; e < 4; e++) acc[mt][nt][e] = 0.f;

    const uint32_t* Wf = g_wfrag;  // eW1
#pragma unroll 4
    for (int ks = 0; ks < KS; ks++) {
        uint4 af[4];
        uint2 bf[4];
#pragma unroll
        for (int mt = 0; mt < 4; mt++)
            af[mt] = *(const uint4*)&A2[(((wm * 4 + mt) * KS + ks) * 32 + lane) * 4];
#pragma unroll
        for (int nt = 0; nt < 4; nt++)
            bf[nt] = __ldg((const uint2*)&Wf[((ks * 16 + wn * 4 + nt) * 32 + lane) * 2]);
#pragma unroll
        for (int mt = 0; mt < 4; mt++)
#pragma unroll
            for (int nt = 0; nt < 4; nt++)
                mma_tf32(acc[mt][nt], (const uint32_t*)&af[mt], (const uint32_t*)&bf[nt]);
    }

    int g = lane >> 2, t4 = lane & 3;
#pragma unroll
    for (int nt = 0; nt < 4; nt++) {
        int cc = wn * 32 + nt * 8 + t4 * 2;
        float b0 = sB[cc], b1 = sB[cc + 1];
        float s0 = 0.f, q0 = 0.f, s1 = 0.f, q1 = 0.f;
#pragma unroll
        for (int mt = 0; mt < 4; mt++) {
            int gr = rbase + wm * 64 + mt * 16 + g;
            float v0 = acc[mt][nt][0] + b0, v1 = acc[mt][nt][1] + b1;
            float v2 = acc[mt][nt][2] + b0, v3 = acc[mt][nt][3] + b1;
            *(__nv_bfloat162*)(g_bufA + (size_t)gr * 128 + cc) = __floats2bfloat162_rn(v0, v1);
            *(__nv_bfloat162*)(g_bufA + (size_t)(gr + 8) * 128 + cc) = __floats2bfloat162_rn(v2, v3);
            s0 += v0 + v2; q0 += v0 * v0 + v2 * v2;
            s1 += v1 + v3; q1 += v1 * v1 + v3 * v3;
        }
        atomicAdd(&xcs[cc], s0);
        atomicAdd(&xcq[cc], q0);
        atomicAdd(&xcs[cc + 1], s1);
        atomicAdd(&xcq[cc + 1], q1);
    }
    __syncthreads();
    if (tid < 128) {
        atomicAdd(&g_stat[96 + tid], xcs[tid]);
        atomicAdd(&g_stat[224 + tid], xcq[tid]);
    }
}

__global__ void __launch_bounds__(256)
gemm_fuse(const float* __restrict__ bias1, const float* __restrict__ bias2,
          const int* __restrict__ i0) {
    constexpr int KS2 = 22;  // stage-2 K = 176
    extern __shared__ __align__(16) uint32_t dynsm[];
    uint32_t* A2 = dynsm;                 // 22528 u32
    uint32_t* As1 = dynsm + 22528;        // 16384 u32 (FULL stage-1 A, K=128)
    __shared__ float xcs[128], xcq[128];
    __shared__ int sI0[128];
    __shared__ float sSc[128], sSh[128], sB1[128], sB2[128];

    int tid = threadIdx.x;
    int lane = tid & 31, w = tid >> 5;
    int wm = w >> 2, wn = w & 3;
    int rbase = blockIdx.x * 128;
    int g = lane >> 2, t4 = lane & 3;

    if (tid < 128) {
        xcs[tid] = 0.f;
        xcq[tid] = 0.f;
        sB1[tid] = bias1[tid];
        sB2[tid] = bias2[tid];
        sI0[tid] = clampi(i0[rbase + tid], NN);
        sSc[tid] = g_ss[96 + tid];
        sSh[tid] = g_ss[224 + tid];
    }
    __syncthreads();

    // pack stage-2 A cols 0..47 (ks 0..5) from xbn[row] (pre-rounded tf32, no cvt)
#pragma unroll
    for (int it = 0; it < 6; it++) {
        int v = tid + it * 256;
        int r = v / 12, q = v % 12;
        float4 val = *(const float4*)(g_xbn + (size_t)sI0[r] * 48 + q * 4);
        int base = a2idx(KS2, r, q >> 1, (q & 1) * 4);
        A2[base + 0] = __float_as_uint(val.x);
        A2[base + 4] = __float_as_uint(val.y);
        A2[base + 8] = __float_as_uint(val.z);
        A2[base + 12] = __float_as_uint(val.w);
    }

    // stage-1 FULL pack: BNrelu(h1[bf16]) -> As1, K=128 (16 ks), batched loads
#pragma unroll
    for (int it = 0; it < 8; it++) {
        int v = tid + it * 256;
        int r = v >> 4, ql = v & 15;
        int c0 = ql * 8;
        float f[8];
        ld_bf16x8(g_bufA + (size_t)(rbase + r) * 128 + c0, f);
#pragma unroll
        for (int kk = 0; kk < 8; kk++) {
            float val = fmaxf(f[kk] * sSc[c0 + kk] + sSh[c0 + kk], 0.f);
            As1[a2idx(16, r, ql, kk)] = to_tf32(val);
        }
    }
    __syncthreads();

    // ---- stage 1: edge_attr = As1 @ eW2 + eb2 (straight 16-ks mainloop) ----
    float acc[4][4][4];
#pragma unroll
    for (int mt = 0; mt < 4; mt++)
#pragma unroll
        for (int nt = 0; nt < 4; nt++)
#pragma unroll
            for (int e = 0; e < 4; e++) acc[mt][nt][e] = 0.f;

    const uint32_t* Wf1 = g_wfrag + 12288;  // eW2
#pragma unroll 4
    for (int ks = 0; ks < 16; ks++) {
        uint4 af[4];
        uint2 bf[4];
#pragma unroll
        for (int mt = 0; mt < 4; mt++)
            af[mt] = *(const uint4*)&As1[(((wm * 4 + mt) * 16 + ks) * 32 + lane) * 4];
#pragma unroll
        for (int nt = 0; nt < 4; nt++)
            bf[nt] = __ldg((const uint2*)&Wf1[((ks * 16 + wn * 4 + nt) * 32 + lane) * 2]);
#pragma unroll
        for (int mt = 0; mt < 4; mt++)
#pragma unroll
            for (int nt = 0; nt < 4; nt++)
                mma_tf32(acc[mt][nt], (const uint32_t*)&af[mt], (const uint32_t*)&bf[nt]);
    }

    // stage-1 epilogue: edge_attr -> A2 fragments (k = 48 + col)
#pragma unroll
    for (int nt = 0; nt < 4; nt++) {
        int cc = wn * 32 + nt * 8 + t4 * 2;
        int ks = 6 + wn * 4 + nt;
        float b0 = sB1[cc], b1 = sB1[cc + 1];
        int kk0 = t4 * 2, kk1 = t4 * 2 + 1;
#pragma unroll
        for (int mt = 0; mt < 4; mt++) {
            int r0 = wm * 64 + mt * 16 + g;
            A2[a2idx(KS2, r0, ks, kk0)] = to_tf32(acc[mt][nt][0] + b0);
            A2[a2idx(KS2, r0, ks, kk1)] = to_tf32(acc[mt][nt][1] + b1);
            A2[a2idx(KS2, r0 + 8, ks, kk0)] = to_tf32(acc[mt][nt][2] + b0);
            A2[a2idx(KS2, r0 + 8, ks, kk1)] = to_tf32(acc[mt][nt][3] + b1);
        }
    }
    __syncthreads();

    // ---- stage 2: h2 = cat(xbn, edge_attr) @ n1W1 + n1b1 ----
    float ac2[4][4][4];
#pragma unroll
    for (int mt = 0; mt < 4; mt++)
#pragma unroll
        for (int nt = 0; nt < 4; nt++)
#pragma unroll
            for (int e = 0; e < 4; e++) ac2[mt][nt][e] = 0.f;

    const uint32_t* Wf2 = g_wfrag + 28672;  // n1W1
#pragma unroll 2
    for (int ks = 0; ks < KS2; ks++) {
        uint4 af[4];
        uint2 bf[4];
#pragma unroll
        for (int mt = 0; mt < 4; mt++)
            af[mt] = *(const uint4*)&A2[(((wm * 4 + mt) * KS2 + ks) * 32 + lane) * 4];
#pragma unroll
        for (int nt = 0; nt < 4; nt++)
            bf[nt] = __ldg((const uint2*)&Wf2[((ks * 16 + wn * 4 + nt) * 32 + lane) * 2]);
#pragma unroll
        for (int mt = 0; mt < 4; mt++)
#pragma unroll
            for (int nt = 0; nt < 4; nt++)
                mma_tf32(ac2[mt][nt], (const uint32_t*)&af[mt], (const uint32_t*)&bf[nt]);
    }

    // stage-2 epilogue: store h2 (bf16) + stats (fp32)
#pragma unroll
    for (int nt = 0; nt < 4; nt++) {
        int cc = wn * 32 + nt * 8 + t4 * 2;
        float b0 = sB2[cc], b1 = sB2[cc + 1];
        float s0 = 0.f, q0 = 0.f, s1 = 0.f, q1 = 0.f;
#pragma unroll
        for (int mt = 0; mt < 4; mt++) {
            int gr = rbase + wm * 64 + mt * 16 + g;
            float v0 = ac2[mt][nt][0] + b0, v1 = ac2[mt][nt][1] + b1;
            float v2 = ac2[mt][nt][2] + b0, v3 = ac2[mt][nt][3] + b1;
            *(__nv_bfloat162*)(g_bufA + (size_t)gr * 128 + cc) = __floats2bfloat162_rn(v0, v1);
            *(__nv_bfloat162*)(g_bufA + (size_t)(gr + 8) * 128 + cc) = __floats2bfloat162_rn(v2, v3);
            s0 += v0 + v2; q0 += v0 * v0 + v2 * v2;
            s1 += v1 + v3; q1 += v1 * v1 + v3 * v3;
        }
        atomicAdd(&xcs[cc], s0);
        atomicAdd(&xcq[cc], q0);
        atomicAdd(&xcs[cc + 1], s1);
        atomicAdd(&xcq[cc + 1], q1);
    }
    __syncthreads();
    if (tid < 128) {
        atomicAdd(&g_stat[352 + tid], xcs[tid]);
        atomicAdd(&g_stat[480 + tid], xcq[tid]);
    }
}

__global__ void __launch_bounds__(256, 2)
gemm_n1l2(const float* __restrict__ bias, const int* __restrict__ i1) {
    constexpr int KS = 16;
    extern __shared__ __align__(16) uint32_t A2[];
    __shared__ int sI1[128];
    __shared__ float sSc[128], sSh[128], sB[128];

    int tid = threadIdx.x;
    int lane = tid & 31, w = tid >> 5;
    int wm = w >> 2, wn = w & 3;
    int rbase = blockIdx.x * 128;

    if (tid < 128) {
        sB[tid] = bias[tid];
        sI1[tid] = clampi(i1[rbase + tid], NN);
        sSc[tid] = g_ss[352 + tid];
        sSh[tid] = g_ss[480 + tid];
    }
    __syncthreads();

#pragma unroll
    for (int it = 0; it < 8; it++) {
        int v = tid + it * 256;
        int r = v >> 4, ql = v & 15;
        int c0 = ql * 8;
        float f[8];
        ld_bf16x8(g_bufA + (size_t)(rbase + r) * 128 + c0, f);
#pragma unroll
        for (int kk = 0; kk < 8; kk++) {
            float val = fmaxf(f[kk] * sSc[c0 + kk] + sSh[c0 + kk], 0.f);
            A2[a2idx(KS, r, ql, kk)] = to_tf32(val);
        }
    }
    __syncthreads();

    float acc[4][4][4];
#pragma unroll
    for (int mt = 0; mt < 4; mt++)
#pragma unroll
        for (int nt = 0; nt < 4; nt++)
#pragma unroll
            for (int e = 0; e < 4; e++) acc[mt][nt][e] = 0.f;

    const uint32_t* Wf = g_wfrag + 51200;  // n1W2
#pragma unroll 4
    for (int ks = 0; ks < KS; ks++) {
        uint4 af[4];
        uint2 bf[4];
#pragma unroll
        for (int mt = 0; mt < 4; mt++)
            af[mt] = *(const uint4*)&A2[(((wm * 4 + mt) * KS + ks) * 32 + lane) * 4];
#pragma unroll
        for (int nt = 0; nt < 4; nt++)
            bf[nt] = __ldg((const uint2*)&Wf[((ks * 16 + wn * 4 + nt) * 32 + lane) * 2]);
#pragma unroll
        for (int mt = 0; mt < 4; mt++)
#pragma unroll
            for (int nt = 0; nt < 4; nt++)
                mma_tf32(acc[mt][nt], (const uint32_t*)&af[mt], (const uint32_t*)&bf[nt]);
    }

    int g = lane >> 2, t4 = lane & 3;
#pragma unroll
    for (int mt = 0; mt < 4; mt++) {
        int rl = wm * 64 + mt * 16 + g;
        int t0 = sI1[rl], t1 = sI1[rl + 8];
#pragma unroll
        for (int nt = 0; nt < 4; nt++) {
            int cc = wn * 32 + nt * 8 + t4 * 2;
            float b0 = sB[cc], b1 = sB[cc + 1];
            red2(&g_agg[(size_t)t0 * 128 + cc], acc[mt][nt][0] + b0, acc[mt][nt][1] + b1);
            red2(&g_agg[(size_t)t1 * 128 + cc], acc[mt][nt][2] + b0, acc[mt][nt][3] + b1);
        }
    }
}

// ---------------- node-level mma kernels (391 CTAs, tail-guarded) ----------------

__global__ void __launch_bounds__(256, 2)
gemm_n2l1(const float* __restrict__ bias) {
    constexpr int KS2 = 22;  // K = 176
    extern __shared__ __align__(16) uint32_t A2[];
    __shared__ float xcs[128], xcq[128];
    __shared__ float sInv[128], sB[128];

    int tid = threadIdx.x;
    int lane = tid & 31, w = tid >> 5;
    int wm = w >> 2, wn = w & 3;
    int rbase = blockIdx.x * 128;

    if (tid < 128) {
        int r = rbase + tid;
        xcs[tid] = 0.f;
        xcq[tid] = 0.f;
        sB[tid] = bias[tid];
        sInv[tid] = (r < NN) ? 1.f / fmaxf((float)g_colcnt[r], 1.f) : 0.f;
    }
    __syncthreads();

#pragma unroll
    for (int it = 0; it < 22; it++) {
        int v = tid + it * 256;
        int r = v / 44, q = v % 44;
        int gr = rbase + r;
        float4 val = make_float4(0.f, 0.f, 0.f, 0.f);
        if (gr < NN) {
            if (q < 12) {
                val = *(const float4*)(g_xbn + (size_t)gr * 48 + q * 4);
            } else {
                float4 a = ((const float4*)(g_agg + (size_t)gr * 128))[q - 12];
                float iv = sInv[r];
                val.x = a.x * iv; val.y = a.y * iv; val.z = a.z * iv; val.w = a.w * iv;
            }
        }
        int base = a2idx(KS2, r, q >> 1, (q & 1) * 4);
        A2[base + 0] = to_tf32(val.x);
        A2[base + 4] = to_tf32(val.y);
        A2[base + 8] = to_tf32(val.z);
        A2[base + 12] = to_tf32(val.w);
    }
    __syncthreads();

    float acc[4][4][4];
#pragma unroll
    for (int mt = 0; mt < 4; mt++)
#pragma unroll
        for (int nt = 0; nt < 4; nt++)
#pragma unroll
            for (int e = 0; e < 4; e++) acc[mt][nt][e] = 0.f;

    const uint32_t* Wf = g_wfrag + 67584;  // n2W1
#pragma unroll 2
    for (int ks = 0; ks < KS2; ks++) {
        uint4 af[4];
        uint2 bf[4];
#pragma unroll
        for (int mt = 0; mt < 4; mt++)
            af[mt] = *(const uint4*)&A2[(((wm * 4 + mt) * KS2 + ks) * 32 + lane) * 4];
#pragma unroll
        for (int nt = 0; nt < 4; nt++)
            bf[nt] = __ldg((const uint2*)&Wf[((ks * 16 + wn * 4 + nt) * 32 + lane) * 2]);
#pragma unroll
        for (int mt = 0; mt < 4; mt++)
#pragma unroll
            for (int nt = 0; nt < 4; nt++)
                mma_tf32(acc[mt][nt], (const uint32_t*)&af[mt], (const uint32_t*)&bf[nt]);
    }

    int g = lane >> 2, t4 = lane & 3;
#pragma unroll
    for (int nt = 0; nt < 4; nt++) {
        int cc = wn * 32 + nt * 8 + t4 * 2;
        float b0 = sB[cc], b1 = sB[cc + 1];
        float s0 = 0.f, q0 = 0.f, s1 = 0.f, q1 = 0.f;
#pragma unroll
        for (int mt = 0; mt < 4; mt++) {
            int gr = rbase + wm * 64 + mt * 16 + g;
            float v0 = acc[mt][nt][0] + b0, v1 = acc[mt][nt][1] + b1;
            float v2 = acc[mt][nt][2] + b0, v3 = acc[mt][nt][3] + b1;
            if (gr < NN) {
                *(float2*)(g_h3 + (size_t)gr * 128 + cc) = make_float2(v0, v1);
                s0 += v0; q0 += v0 * v0; s1 += v1; q1 += v1 * v1;
            }
            if (gr + 8 < NN) {
                *(float2*)(g_h3 + (size_t)(gr + 8) * 128 + cc) = make_float2(v2, v3);
                s0 += v2; q0 += v2 * v2; s1 += v3; q1 += v3 * v3;
            }
        }
        atomicAdd(&xcs[cc], s0);
        atomicAdd(&xcq[cc], q0);
        atomicAdd(&xcs[cc + 1], s1);
        atomicAdd(&xcq[cc + 1], q1);
    }
    __syncthreads();
    if (tid < 128) {
        atomicAdd(&g_stat[608 + tid], xcs[tid]);
        atomicAdd(&g_stat[736 + tid], xcq[tid]);
    }
}

__global__ void __launch_bounds__(256, 2)
gemm_n2l2(const float* __restrict__ bias, const int* __restrict__ batch) {
    constexpr int KS = 16;
    extern __shared__ __align__(16) uint32_t A2[];
    __shared__ int sI1[128];
    __shared__ float sSc[128], sSh[128], sB[128];

    int tid = threadIdx.x;
    int lane = tid & 31, w = tid >> 5;
    int wm = w >> 2, wn = w & 3;
    int rbase = blockIdx.x * 128;

    if (tid < 128) {
        int r = rbase + tid;
        sB[tid] = bias[tid];
        sI1[tid] = (r < NN) ? clampi(batch[r], GG) : 0;
        sSc[tid] = g_ss[608 + tid];
        sSh[tid] = g_ss[736 + tid];
    }
    __syncthreads();

#pragma unroll
    for (int it = 0; it < 16; it++) {
        int v = tid + it * 256;
        int r = v >> 5, q = v & 31;
        int gr = rbase + r;
        float4 val = make_float4(0.f, 0.f, 0.f, 0.f);
        if (gr < NN) {
            float4 h = ((const float4*)(g_h3 + (size_t)gr * 128))[q];
            int c = q * 4;
            val.x = fmaxf(h.x * sSc[c + 0] + sSh[c + 0], 0.f);
            val.y = fmaxf(h.y * sSc[c + 1] + sSh[c + 1], 0.f);
            val.z = fmaxf(h.z * sSc[c + 2] + sSh[c + 2], 0.f);
            val.w = fmaxf(h.w * sSc[c + 3] + sSh[c + 3], 0.f);
        }
        int base = a2idx(KS, r, q >> 1, (q & 1) * 4);
        A2[base + 0] = to_tf32(val.x);
        A2[base + 4] = to_tf32(val.y);
        A2[base + 8] = to_tf32(val.z);
        A2[base + 12] = to_tf32(val.w);
    }
    __syncthreads();

    float acc[4][4][4];
#pragma unroll
    for (int mt = 0; mt < 4; mt++)
#pragma unroll
        for (int nt = 0; nt < 4; nt++)
#pragma unroll
            for (int e = 0; e < 4; e++) acc[mt][nt][e] = 0.f;

    const uint32_t* Wf = g_wfrag + 90112;  // n2W2
#pragma unroll 4
    for (int ks = 0; ks < KS; ks++) {
        uint4 af[4];
        uint2 bf[4];
#pragma unroll
        for (int mt = 0; mt < 4; mt++)
            af[mt] = *(const uint4*)&A2[(((wm * 4 + mt) * KS + ks) * 32 + lane) * 4];
#pragma unroll
        for (int nt = 0; nt < 4; nt++)
            bf[nt] = __ldg((const uint2*)&Wf[((ks * 16 + wn * 4 + nt) * 32 + lane) * 2]);
#pragma unroll
        for (int mt = 0; mt < 4; mt++)
#pragma unroll
            for (int nt = 0; nt < 4; nt++)
                mma_tf32(acc[mt][nt], (const uint32_t*)&af[mt], (const uint32_t*)&bf[nt]);
    }

    int g = lane >> 2, t4 = lane & 3;
#pragma unroll
    for (int mt = 0; mt < 4; mt++) {
        int rl = wm * 64 + mt * 16 + g;
        int gr0 = rbase + rl, gr1 = gr0 + 8;
        int t0 = sI1[rl], t1 = sI1[rl + 8];
#pragma unroll
        for (int nt = 0; nt < 4; nt++) {
            int cc = wn * 32 + nt * 8 + t4 * 2;
            float b0 = sB[cc], b1 = sB[cc + 1];
            if (gr0 < NN) red2(&g_usum[(size_t)t0 * 128 + cc], acc[mt][nt][0] + b0, acc[mt][nt][1] + b1);
            if (gr1 < NN) red2(&g_usum[(size_t)t1 * 128 + cc], acc[mt][nt][2] + b0, acc[mt][nt][3] + b1);
        }
    }
}

// ---------------- FFMA2 SGEMM for the tiny global layer ----------------
#define KC 32
#define LDT 132

__global__ void __launch_bounds__(256, 2)
gemm_gl1(const float* __restrict__ W, const float* __restrict__ bias) {
    __shared__ __align__(16) float Ast[KC * LDT];
    __shared__ __align__(16) float Ws[KC * 128];
    __shared__ float xcs[128], xcq[128];
    __shared__ float sInv[128];

    int tid = threadIdx.x;
    int tx = tid & 15, ty = tid >> 4;
    int rbase = blockIdx.x * 128;

    if (tid < 128) {
        int r = rbase + tid;
        xcs[tid] = 0.f;
        xcq[tid] = 0.f;
        sInv[tid] = (r < GG) ? 1.f / fmaxf((float)g_gcnt[r], 1.f) : 0.f;
    }
    __syncthreads();

    u64 accp[4][8];
#pragma unroll
    for (int p = 0; p < 4; p++)
#pragma unroll
        for (int j = 0; j < 8; j++) accp[p][j] = 0ull;

#pragma unroll
    for (int kb = 0; kb < 128; kb += KC) {
        for (int v = tid; v < KC * 32; v += 256)
            ((float4*)Ws)[v] = ((const float4*)(W + (size_t)kb * 128))[v];

        for (int v = tid; v < 128 * 8; v += 256) {
            int r = v / 8, ql = v % 8;
            int q = kb / 4 + ql;
            int gr = rbase + r;
            float4 val = make_float4(0.f, 0.f, 0.f, 0.f);
            if (gr < GG) {
                float4 a = ((const float4*)(g_usum + (size_t)gr * 128))[q];
                float iv = sInv[r];
                val.x = a.x * iv; val.y = a.y * iv; val.z = a.z * iv; val.w = a.w * iv;
            }
            int kl = ql * 4;
            Ast[(kl + 0) * LDT + r] = val.x;
            Ast[(kl + 1) * LDT + r] = val.y;
            Ast[(kl + 2) * LDT + r] = val.z;
            Ast[(kl + 3) * LDT + r] = val.w;
        }
        __syncthreads();

        const float* Wp = Ws + tx * 8;
        const float* Ap = Ast + ty * 8;
#pragma unroll
        for (int k = 0; k < KC; k++) {
            float4 b0 = *(const float4*)(Wp + k * 128);
            float4 b1 = *(const float4*)(Wp + k * 128 + 4);
            u64 bd[8];
            bd[0] = pack2(b0.x, b0.x); bd[1] = pack2(b0.y, b0.y);
            bd[2] = pack2(b0.z, b0.z); bd[3] = pack2(b0.w, b0.w);
            bd[4] = pack2(b1.x, b1.x); bd[5] = pack2(b1.y, b1.y);
            bd[6] = pack2(b1.z, b1.z); bd[7] = pack2(b1.w, b1.w);
            ulonglong2 aA = *(const ulonglong2*)(Ap + k * LDT);
            ulonglong2 aB = *(const ulonglong2*)(Ap + k * LDT + 4);
            u64 ap[4] = {aA.x, aA.y, aB.x, aB.y};
#pragma unroll
            for (int p = 0; p < 4; p++)
#pragma unroll
                for (int j = 0; j < 8; j++) ffma2(accp[p][j], ap[p], bd[j]);
        }
        __syncthreads();
    }

    float acc[8][8];
#pragma unroll
    for (int p = 0; p < 4; p++)
#pragma unroll
        for (int j = 0; j < 8; j++)
            unpack2(accp[p][j], acc[2 * p][j], acc[2 * p + 1][j]);

    int cb = tx * 8;
    float bs[8];
#pragma unroll
    for (int j = 0; j < 8; j++) bs[j] = bias[cb + j];
#pragma unroll
    for (int i = 0; i < 8; i++)
#pragma unroll
        for (int j = 0; j < 8; j++) acc[i][j] += bs[j];

    float s[8], q[8];
#pragma unroll
    for (int j = 0; j < 8; j++) { s[j] = 0.f; q[j] = 0.f; }
#pragma unroll
    for (int i = 0; i < 8; i++) {
        int gr = rbase + ty * 8 + i;
        if (gr < GG) {
            *(float4*)(g_hg + (size_t)gr * 128 + cb) = make_float4(acc[i][0], acc[i][1], acc[i][2], acc[i][3]);
            *(float4*)(g_hg + (size_t)gr * 128 + cb + 4) = make_float4(acc[i][4], acc[i][5], acc[i][6], acc[i][7]);
#pragma unroll
            for (int j = 0; j < 8; j++) {
                s[j] += acc[i][j];
                q[j] += acc[i][j] * acc[i][j];
            }
        }
    }
#pragma unroll
    for (int j = 0; j < 8; j++) {
        atomicAdd(&xcs[cb + j], s[j]);
        atomicAdd(&xcq[cb + j], q[j]);
    }
    __syncthreads();
    if (tid < 128) {
        atomicAdd(&g_stat[864 + tid], xcs[tid]);
        atomicAdd(&g_stat[992 + tid], xcq[tid]);
    }
}

__global__ void glout_k(const float* __restrict__ W2, const float* __restrict__ b2,
                        float* __restrict__ out) {
    int g = threadIdx.x;
    float a0 = 0.f, a1 = 0.f;
    for (int c = 0; c < 128; c++) {
        float h = fmaxf(g_hg[g * 128 + c] * g_ss[864 + c] + g_ss[992 + c], 0.f);
        a0 = fmaf(h, W2[c * 2 + 0], a0);
        a1 = fmaf(h, W2[c * 2 + 1], a1);
    }
    out[g * 2 + 0] = a0 + b2[0];
    out[g * 2 + 1] = a1 + b2[1];
}

// ---------------- host ----------------
extern "C" void kernel_launch(void* const* d_in, const int* in_sizes, int n_in,
                              void* d_out, int out_size) {
    (void)in_sizes; (void)n_in; (void)out_size;
    const float* x = (const float*)d_in[0];
    const int* ei = (const int*)d_in[1];
    const int* batch = (const int*)d_in[2];
    const float* bn_g = (const float*)d_in[3];
    const float* bn_b = (const float*)d_in[4];
    const float* eW1 = (const float*)d_in[5];
    const float* eb1 = (const float*)d_in[6];
    const float* eg = (const float*)d_in[7];
    const float* ebe = (const float*)d_in[8];
    const float* eW2 = (const float*)d_in[9];
    const float* eb2 = (const float*)d_in[10];
    const float* n1W1 = (const float*)d_in[11];
    const float* n1b1 = (const float*)d_in[12];
    const float* n1g = (const float*)d_in[13];
    const float* n1be = (const float*)d_in[14];
    const float* n1W2 = (const float*)d_in[15];
    const float* n1b2 = (const float*)d_in[16];
    const float* n2W1 = (const float*)d_in[17];
    const float* n2b1 = (const float*)d_in[18];
    const float* n2g = (const float*)d_in[19];
    const float* n2be = (const float*)d_in[20];
    const float* n2W2 = (const float*)d_in[21];
    const float* n2b2 = (const float*)d_in[22];
    const float* glW1 = (const float*)d_in[23];
    const float* glb1 = (const float*)d_in[24];
    const float* glg = (const float*)d_in[25];
    const float* glbe = (const float*)d_in[26];
    const float* glW2 = (const float*)d_in[27];
    const float* glb2 = (const float*)d_in[28];

    const int* row = ei;
    const int* col = ei + EE;

    const int EB = EE / 128;          // 12500
    const int NB = (NN + 127) / 128;  // 391

    const int SM_E1 = 12 * 4096;      // 49152
    const int SM_FUSE = 38912 * 4;    // 155648
    const int SM_N1L2 = 16 * 4096;    // 65536
    const int SM_N2L1 = 22 * 4096;    // 90112
    cudaFuncSetAttribute(gemm_e1, cudaFuncAttributeMaxDynamicSharedMemorySize, SM_E1);
    cudaFuncSetAttribute(gemm_fuse, cudaFuncAttributeMaxDynamicSharedMemorySize, SM_FUSE);
    cudaFuncSetAttribute(gemm_n1l2, cudaFuncAttributeMaxDynamicSharedMemorySize, SM_N1L2);
    cudaFuncSetAttribute(gemm_n2l1, cudaFuncAttributeMaxDynamicSharedMemorySize, SM_N2L1);
    cudaFuncSetAttribute(gemm_n2l2, cudaFuncAttributeMaxDynamicSharedMemorySize, SM_N1L2);

    zero_k<<<2048, 256>>>();
    xstats_k<<<512, 256>>>(x);
    finalize_k<<<1, 48>>>(bn_g, bn_b, 0, 0, 48, 48, (float)NN);
    xbn_k<<<2048, 256>>>(x);
    count_k<<<2048, 256>>>(col, batch);
    prep_all<<<148, 256>>>(eW1, eW2, n1W1, n1W2, n2W1, n2W2);

    gemm_e1<<<EB, 256, SM_E1>>>(eb1, row, col);
    finalize_k<<<1, 128>>>(eg, ebe, 96, 96, 224, 128, (float)EE);
    gemm_fuse<<<EB, 256, SM_FUSE>>>(eb2, n1b1, row);
    finalize_k<<<1, 128>>>(n1g, n1be, 352, 352, 480, 128, (float)EE);
    gemm_n1l2<<<EB, 256, SM_N1L2>>>(n1b2, col);

    gemm_n2l1<<<NB, 256, SM_N2L1>>>(n2b1);
    finalize_k<<<1, 128>>>(n2g, n2be, 608, 608, 736, 128, (float)NN);
    gemm_n2l2<<<NB, 256, SM_N1L2>>>(n2b2, batch);
    gemm_gl1<<<2, 256>>>(glW1, glb1);
    finalize_k<<<1, 128>>>(glg, glbe, 864, 864, 992, 128, 256.f);
    glout_k<<<1, 256>>>(glW2, glb2, (float*)d_out);
}

// round 17
// speedup vs baseline: 1.1424x; 1.1424x over previous
#include <cuda_runtime.h>
#include <cuda_bf16.h>
#include <cstddef>
#include <cstdint>

#define NN 50000
#define EE 1600000
#define GG 256
#define EPSV 1e-5f

typedef unsigned long long u64;

// ---------------- ptx helpers ----------------
__device__ __forceinline__ u64 pack2(float lo, float hi) {
    u64 r;
    asm("mov.b64 %0, {%1, %2};" : "=l"(r) : "f"(lo), "f"(hi));
    return r;
}
__device__ __forceinline__ void unpack2(u64 v, float& lo, float& hi) {
    asm("mov.b64 {%0, %1}, %2;" : "=f"(lo), "=f"(hi) : "l"(v));
}
__device__ __forceinline__ void ffma2(u64& d, u64 a, u64 b) {
    asm("fma.rn.f32x2 %0, %1, %2, %0;" : "+l"(d) : "l"(a), "l"(b));
}
__device__ __forceinline__ uint32_t to_tf32(float f) {
    uint32_t u;
    asm("cvt.rna.tf32.f32 %0, %1;" : "=r"(u) : "f"(f));
    return u;
}
__device__ __forceinline__ void mma_tf32(float* c, const uint32_t* a, const uint32_t* b) {
    asm volatile(
        "mma.sync.aligned.m16n8k8.row.col.f32.tf32.tf32.f32 "
        "{%0,%1,%2,%3}, {%4,%5,%6,%7}, {%8,%9}, {%0,%1,%2,%3};"
        : "+f"(c[0]), "+f"(c[1]), "+f"(c[2]), "+f"(c[3])
        : "r"(a[0]), "r"(a[1]), "r"(a[2]), "r"(a[3]), "r"(b[0]), "r"(b[1]));
}
__device__ __forceinline__ void red2(float* addr, float a, float b) {
    asm volatile("red.global.add.v2.f32 [%0], {%1, %2};" :: "l"(addr), "f"(a), "f"(b) : "memory");
}

// ---------------- device scratch ----------------
__device__ __align__(16) float g_xbn[NN * 48];            // pre-rounded to tf32 (all consumers re-cvt or copy)
__device__ __align__(16) __nv_bfloat16 g_bufA[(size_t)EE * 128];  // h1 -> h2 (bf16)
__device__ __align__(16) float g_h3[50048 * 128];
__device__ __align__(16) float g_agg[NN * 128];
__device__ __align__(16) float g_usum[GG * 128];
__device__ __align__(16) float g_hg[GG * 128];
// W frag regions (u32): eW1@0(12ks) eW2@12288(16) n1W1@28672(22) n1W2@51200(16) n2W1@67584(22) n2W2@90112(16)
__device__ __align__(16) uint32_t g_wfrag[106496];
__device__ int   g_colcnt[NN];
__device__ int   g_gcnt[GG];
// stats: x@0(48+48), e@96(128+128), n1@352, n2@608, gl@864
__device__ float g_stat[1120];
// scale/shift: x sc@0 sh@48 ; e sc@96 sh@224 ; n1 sc@352 sh@480 ; n2 sc@608 sh@736 ; gl sc@864 sh@992
__device__ float g_ss[1120];

__device__ __forceinline__ int clampi(int v, int hi) {
    return v < 0 ? 0 : (v >= hi ? hi - 1 : v);
}

// A-fragment u32 index within one 128-row tile
__device__ __forceinline__ int a2idx(int KS, int r, int ks, int kk) {
    return ((((r >> 4) * KS + ks) * 32 + (r & 7) * 4 + (kk & 3)) << 2) +
           (((kk & 4) >> 1) | ((r >> 3) & 1));
}

// ---------------- small kernels ----------------
__global__ void zero_k() {
    size_t i = (size_t)blockIdx.x * blockDim.x + threadIdx.x;
    size_t st = (size_t)gridDim.x * blockDim.x;
    for (size_t j = i; j < (size_t)NN * 128; j += st) g_agg[j] = 0.f;
    for (size_t j = i; j < NN; j += st) g_colcnt[j] = 0;
    for (size_t j = i; j < (size_t)GG * 128; j += st) g_usum[j] = 0.f;
    for (size_t j = i; j < GG; j += st) g_gcnt[j] = 0;
    for (size_t j = i; j < 1120; j += st) g_stat[j] = 0.f;
}

__global__ void xstats_k(const float* __restrict__ x) {
    __shared__ float ss[48], sq[48];
    int t = threadIdx.x;
    if (t < 48) { ss[t] = 0.f; sq[t] = 0.f; }
    __syncthreads();
    long long st = (long long)gridDim.x * blockDim.x;
    for (long long i = (long long)blockIdx.x * blockDim.x + t; i < (long long)NN * 48; i += st) {
        float v = x[i];
        int c = (int)(i % 48);
        atomicAdd(&ss[c], v);
        atomicAdd(&sq[c], v * v);
    }
    __syncthreads();
    if (t < 48) {
        atomicAdd(&g_stat[t], ss[t]);
        atomicAdd(&g_stat[48 + t], sq[t]);
    }
}

__global__ void finalize_k(const float* __restrict__ gamma, const float* __restrict__ beta,
                           int stat_off, int sc_off, int sh_off, int C, float cnt) {
    int c = threadIdx.x;
    if (c < C) {
        float m = g_stat[stat_off + c] / cnt;
        float v = g_stat[stat_off + C + c] / cnt - m * m;
        float s = gamma[c] * rsqrtf(v + EPSV);
        g_ss[sc_off + c] = s;
        g_ss[sh_off + c] = beta[c] - m * s;
    }
}

// store pre-rounded to tf32 (consumers use tf32 mma; re-round is identity)
__global__ void xbn_k(const float* __restrict__ x) {
    long long st = (long long)gridDim.x * blockDim.x;
    for (long long i = (long long)blockIdx.x * blockDim.x + threadIdx.x; i < (long long)NN * 48; i += st) {
        int c = (int)(i % 48);
        g_xbn[i] = __uint_as_float(to_tf32(x[i] * g_ss[c] + g_ss[48 + c]));
    }
}

__global__ void count_k(const int* __restrict__ col, const int* __restrict__ batch) {
    long long st = (long long)gridDim.x * blockDim.x;
    for (long long i = (long long)blockIdx.x * blockDim.x + threadIdx.x; i < EE; i += st)
        atomicAdd(&g_colcnt[clampi(col[i], NN)], 1);
    for (long long i = (long long)blockIdx.x * blockDim.x + threadIdx.x; i < NN; i += st)
        atomicAdd(&g_gcnt[clampi(batch[i], GG)], 1);
}

__device__ __forceinline__ void prep_region(const float* W, int kact, int woff) {
    int stride = gridDim.x * blockDim.x;
    for (int idx = blockIdx.x * blockDim.x + threadIdx.x; idx < kact * 128; idx += stride) {
        int k = idx >> 7, n = idx & 127;
        int ks = k >> 3, kk = k & 7;
        int lane = (kk & 3) + (n & 7) * 4;
        int reg = (kk >= 4) ? 1 : 0;
        g_wfrag[woff + ((ks * 16 + (n >> 3)) * 32 + lane) * 2 + reg] = to_tf32(W[idx]);
    }
}
__global__ void prep_all(const float* __restrict__ eW1, const float* __restrict__ eW2,
                         const float* __restrict__ n1W1, const float* __restrict__ n1W2,
                         const float* __restrict__ n2W1, const float* __restrict__ n2W2) {
    prep_region(eW1, 96, 0);
    prep_region(eW2, 128, 12288);
    prep_region(n1W1, 176, 28672);
    prep_region(n1W2, 128, 51200);
    prep_region(n2W1, 176, 67584);
    prep_region(n2W2, 128, 90112);
}

// load 8 bf16 and expand to floats
__device__ __forceinline__ void ld_bf16x8(const __nv_bfloat16* src, float* f) {
    uint4 raw = *(const uint4*)src;
    float2 t;
    t = __bfloat1622float2(*(__nv_bfloat162*)&raw.x); f[0] = t.x; f[1] = t.y;
    t = __bfloat1622float2(*(__nv_bfloat162*)&raw.y); f[2] = t.x; f[3] = t.y;
    t = __bfloat1622float2(*(__nv_bfloat162*)&raw.z); f[4] = t.x; f[5] = t.y;
    t = __bfloat1622float2(*(__nv_bfloat162*)&raw.w); f[6] = t.x; f[7] = t.y;
}

// ---------------- mma.sync edge kernels (256 threads, 8 warps: 2M x 4N) ----------------

__global__ void __launch_bounds__(256, 2)
gemm_e1(const float* __restrict__ bias, const int* __restrict__ i0,
        const int* __restrict__ i1) {
    constexpr int KS = 12;
    extern __shared__ __align__(16) uint32_t A2[];
    __shared__ float xcs[128], xcq[128];
    __shared__ int sI0[128], sI1[128];
    __shared__ float sB[128];

    int tid = threadIdx.x;
    int lane = tid & 31, w = tid >> 5;
    int wm = w >> 2, wn = w & 3;
    int rbase = blockIdx.x * 128;

    if (tid < 128) {
        xcs[tid] = 0.f;
        xcq[tid] = 0.f;
        sB[tid] = bias[tid];
        sI0[tid] = clampi(i0[rbase + tid], NN);
        sI1[tid] = clampi(i1[rbase + tid], NN);
    }
    __syncthreads();

    // xbn pre-rounded to tf32: pure copy, no cvt
    for (int v = tid; v < 128 * 24; v += 256) {
        int r = v / 24, q = v % 24;
        const float* src = (q < 12) ? (g_xbn + (size_t)sI0[r] * 48 + q * 4)
                                    : (g_xbn + (size_t)sI1[r] * 48 + (q - 12) * 4);
        float4 val = *(const float4*)src;
        int base = a2idx(KS, r, q >> 1, (q & 1) * 4);
        A2[base + 0] = __float_as_uint(val.x);
        A2[base + 4] = __float_as_uint(val.y);
        A2[base + 8] = __float_as_uint(val.z);
        A2[base + 12] = __float_as_uint(val.w);
    }
    __syncthreads();

    float acc[4][4][4];
#pragma unroll
    for (int mt = 0; mt < 4; mt++)
#pragma unroll
        for (int nt = 0; nt < 4; nt++)
#pragma unroll
            for (int e = 0; e < 4; e++) acc[mt][nt][e] = 0.f;

    const uint32_t* Wf = g_wfrag;  // eW1
#pragma unroll 4
    for (int ks = 0; ks < KS; ks++) {
        uint4 af[4];
        uint2 bf[4];
#pragma unroll
        for (int mt = 0; mt < 4; mt++)
            af[mt] = *(const uint4*)&A2[(((wm * 4 + mt) * KS + ks) * 32 + lane) * 4];
#pragma unroll
        for (int nt = 0; nt < 4; nt++)
            bf[nt] = __ldg((const uint2*)&Wf[((ks * 16 + wn * 4 + nt) * 32 + lane) * 2]);
#pragma unroll
        for (int mt = 0; mt < 4; mt++)
#pragma unroll
            for (int nt = 0; nt < 4; nt++)
                mma_tf32(acc[mt][nt], (const uint32_t*)&af[mt], (const uint32_t*)&bf[nt]);
    }

    int g = lane >> 2, t4 = lane & 3;
#pragma unroll
    for (int nt = 0; nt < 4; nt++) {
        int cc = wn * 32 + nt * 8 + t4 * 2;
        float b0 = sB[cc], b1 = sB[cc + 1];
        float s0 = 0.f, q0 = 0.f, s1 = 0.f, q1 = 0.f;
#pragma unroll
        for (int mt = 0; mt < 4; mt++) {
            int gr = rbase + wm * 64 + mt * 16 + g;
            float v0 = acc[mt][nt][0] + b0, v1 = acc[mt][nt][1] + b1;
            float v2 = acc[mt][nt][2] + b0, v3 = acc[mt][nt][3] + b1;
            *(__nv_bfloat162*)(g_bufA + (size_t)gr * 128 + cc) = __floats2bfloat162_rn(v0, v1);
            *(__nv_bfloat162*)(g_bufA + (size_t)(gr + 8) * 128 + cc) = __floats2bfloat162_rn(v2, v3);
            s0 += v0 + v2; q0 += v0 * v0 + v2 * v2;
            s1 += v1 + v3; q1 += v1 * v1 + v3 * v3;
        }
        atomicAdd(&xcs[cc], s0);
        atomicAdd(&xcq[cc], q0);
        atomicAdd(&xcs[cc + 1], s1);
        atomicAdd(&xcq[cc + 1], q1);
    }
    __syncthreads();
    if (tid < 128) {
        atomicAdd(&g_stat[96 + tid], xcs[tid]);
        atomicAdd(&g_stat[224 + tid], xcq[tid]);
    }
}

__global__ void __launch_bounds__(256, 2)
gemm_fuse(const float* __restrict__ bias1, const float* __restrict__ bias2,
          const int* __restrict__ i0) {
    constexpr int KS2 = 22;  // stage-2 K = 176
    extern __shared__ __align__(16) uint32_t dynsm[];
    uint32_t* A2 = dynsm;                 // 22528 u32
    uint32_t* As1 = dynsm + 22528;        // 4096 u32 (4-ks chunk for stage 1)
    __shared__ float xcs[128], xcq[128];
    __shared__ int sI0[128];
    __shared__ float sSc[128], sSh[128], sB1[128], sB2[128];

    int tid = threadIdx.x;
    int lane = tid & 31, w = tid >> 5;
    int wm = w >> 2, wn = w & 3;
    int rbase = blockIdx.x * 128;
    int g = lane >> 2, t4 = lane & 3;

    if (tid < 128) {
        xcs[tid] = 0.f;
        xcq[tid] = 0.f;
        sB1[tid] = bias1[tid];
        sB2[tid] = bias2[tid];
        sI0[tid] = clampi(i0[rbase + tid], NN);
        sSc[tid] = g_ss[96 + tid];
        sSh[tid] = g_ss[224 + tid];
    }
    __syncthreads();

    // pack stage-2 A cols 0..47 (ks 0..5) from xbn[row] (pre-rounded, pure copy)
    for (int v = tid; v < 128 * 12; v += 256) {
        int r = v / 12, q = v % 12;
        float4 val = *(const float4*)(g_xbn + (size_t)sI0[r] * 48 + q * 4);
        int base = a2idx(KS2, r, q >> 1, (q & 1) * 4);
        A2[base + 0] = __float_as_uint(val.x);
        A2[base + 4] = __float_as_uint(val.y);
        A2[base + 8] = __float_as_uint(val.z);
        A2[base + 12] = __float_as_uint(val.w);
    }

    // ---- stage 1: edge_attr = BNrelu(h1[bf16]) @ eW2 + eb2 (chunked) ----
    float acc[4][4][4];
#pragma unroll
    for (int mt = 0; mt < 4; mt++)
#pragma unroll
        for (int nt = 0; nt < 4; nt++)
#pragma unroll
            for (int e = 0; e < 4; e++) acc[mt][nt][e] = 0.f;

    const uint32_t* Wf1 = g_wfrag + 12288;  // eW2
    for (int kb = 0; kb < 128; kb += 32) {
        for (int v = tid; v < 128 * 4; v += 256) {
            int r = v >> 2, ql = v & 3;
            int c0 = kb + ql * 8;
            float f[8];
            ld_bf16x8(g_bufA + (size_t)(rbase + r) * 128 + c0, f);
#pragma unroll
            for (int kk = 0; kk < 8; kk++) {
                float val = fmaxf(f[kk] * sSc[c0 + kk] + sSh[c0 + kk], 0.f);
                As1[a2idx(4, r, ql, kk)] = to_tf32(val);
            }
        }
        __syncthreads();
        int ksg = kb >> 3;
#pragma unroll
        for (int ks = 0; ks < 4; ks++) {
            uint4 af[4];
            uint2 bf[4];
#pragma unroll
            for (int mt = 0; mt < 4; mt++)
                af[mt] = *(const uint4*)&As1[(((wm * 4 + mt) * 4 + ks) * 32 + lane) * 4];
#pragma unroll
            for (int nt = 0; nt < 4; nt++)
                bf[nt] = __ldg((const uint2*)&Wf1[(((ksg + ks) * 16 + wn * 4 + nt) * 32 + lane) * 2]);
#pragma unroll
            for (int mt = 0; mt < 4; mt++)
#pragma unroll
                for (int nt = 0; nt < 4; nt++)
                    mma_tf32(acc[mt][nt], (const uint32_t*)&af[mt], (const uint32_t*)&bf[nt]);
        }
        __syncthreads();
    }

    // stage-1 epilogue: edge_attr -> A2 fragments (k = 48 + col)
#pragma unroll
    for (int nt = 0; nt < 4; nt++) {
        int cc = wn * 32 + nt * 8 + t4 * 2;
        int ks = 6 + wn * 4 + nt;
        float b0 = sB1[cc], b1 = sB1[cc + 1];
        int kk0 = t4 * 2, kk1 = t4 * 2 + 1;
#pragma unroll
        for (int mt = 0; mt < 4; mt++) {
            int r0 = wm * 64 + mt * 16 + g;
            A2[a2idx(KS2, r0, ks, kk0)] = to_tf32(acc[mt][nt][0] + b0);
            A2[a2idx(KS2, r0, ks, kk1)] = to_tf32(acc[mt][nt][1] + b1);
            A2[a2idx(KS2, r0 + 8, ks, kk0)] = to_tf32(acc[mt][nt][2] + b0);
            A2[a2idx(KS2, r0 + 8, ks, kk1)] = to_tf32(acc[mt][nt][3] + b1);
        }
    }
    __syncthreads();

    // ---- stage 2: h2 = cat(xbn, edge_attr) @ n1W1 + n1b1 ----
    float ac2[4][4][4];
#pragma unroll
    for (int mt = 0; mt < 4; mt++)
#pragma unroll
        for (int nt = 0; nt < 4; nt++)
#pragma unroll
            for (int e = 0; e < 4; e++) ac2[mt][nt][e] = 0.f;

    const uint32_t* Wf2 = g_wfrag + 28672;  // n1W1
#pragma unroll 2
    for (int ks = 0; ks < KS2; ks++) {
        uint4 af[4];
        uint2 bf[4];
#pragma unroll
        for (int mt = 0; mt < 4; mt++)
            af[mt] = *(const uint4*)&A2[(((wm * 4 + mt) * KS2 + ks) * 32 + lane) * 4];
#pragma unroll
        for (int nt = 0; nt < 4; nt++)
            bf[nt] = __ldg((const uint2*)&Wf2[((ks * 16 + wn * 4 + nt) * 32 + lane) * 2]);
#pragma unroll
        for (int mt = 0; mt < 4; mt++)
#pragma unroll
            for (int nt = 0; nt < 4; nt++)
                mma_tf32(ac2[mt][nt], (const uint32_t*)&af[mt], (const uint32_t*)&bf[nt]);
    }

    // stage-2 epilogue: store h2 (bf16) + stats (fp32)
#pragma unroll
    for (int nt = 0; nt < 4; nt++) {
        int cc = wn * 32 + nt * 8 + t4 * 2;
        float b0 = sB2[cc], b1 = sB2[cc + 1];
        float s0 = 0.f, q0 = 0.f, s1 = 0.f, q1 = 0.f;
#pragma unroll
        for (int mt = 0; mt < 4; mt++) {
            int gr = rbase + wm * 64 + mt * 16 + g;
            float v0 = ac2[mt][nt][0] + b0, v1 = ac2[mt][nt][1] + b1;
            float v2 = ac2[mt][nt][2] + b0, v3 = ac2[mt][nt][3] + b1;
            *(__nv_bfloat162*)(g_bufA + (size_t)gr * 128 + cc) = __floats2bfloat162_rn(v0, v1);
            *(__nv_bfloat162*)(g_bufA + (size_t)(gr + 8) * 128 + cc) = __floats2bfloat162_rn(v2, v3);
            s0 += v0 + v2; q0 += v0 * v0 + v2 * v2;
            s1 += v1 + v3; q1 += v1 * v1 + v3 * v3;
        }
        atomicAdd(&xcs[cc], s0);
        atomicAdd(&xcq[cc], q0);
        atomicAdd(&xcs[cc + 1], s1);
        atomicAdd(&xcq[cc + 1], q1);
    }
    __syncthreads();
    if (tid < 128) {
        atomicAdd(&g_stat[352 + tid], xcs[tid]);
        atomicAdd(&g_stat[480 + tid], xcq[tid]);
    }
}

__global__ void __launch_bounds__(256, 2)
gemm_n1l2(const float* __restrict__ bias, const int* __restrict__ i1) {
    constexpr int KS = 16;
    extern __shared__ __align__(16) uint32_t A2[];
    __shared__ int sI1[128];
    __shared__ float sSc[128], sSh[128], sB[128];

    int tid = threadIdx.x;
    int lane = tid & 31, w = tid >> 5;
    int wm = w >> 2, wn = w & 3;
    int rbase = blockIdx.x * 128;

    if (tid < 128) {
        sB[tid] = bias[tid];
        sI1[tid] = clampi(i1[rbase + tid], NN);
        sSc[tid] = g_ss[352 + tid];
        sSh[tid] = g_ss[480 + tid];
    }
    __syncthreads();

    for (int v = tid; v < 128 * 16; v += 256) {
        int r = v >> 4, ql = v & 15;
        int c0 = ql * 8;
        float f[8];
        ld_bf16x8(g_bufA + (size_t)(rbase + r) * 128 + c0, f);
#pragma unroll
        for (int kk = 0; kk < 8; kk++) {
            float val = fmaxf(f[kk] * sSc[c0 + kk] + sSh[c0 + kk], 0.f);
            A2[a2idx(KS, r, ql, kk)] = to_tf32(val);
        }
    }
    __syncthreads();

    float acc[4][4][4];
#pragma unroll
    for (int mt = 0; mt < 4; mt++)
#pragma unroll
        for (int nt = 0; nt < 4; nt++)
#pragma unroll
            for (int e = 0; e < 4; e++) acc[mt][nt][e] = 0.f;

    const uint32_t* Wf = g_wfrag + 51200;  // n1W2
#pragma unroll 4
    for (int ks = 0; ks < KS; ks++) {
        uint4 af[4];
        uint2 bf[4];
#pragma unroll
        for (int mt = 0; mt < 4; mt++)
            af[mt] = *(const uint4*)&A2[(((wm * 4 + mt) * KS + ks) * 32 + lane) * 4];
#pragma unroll
        for (int nt = 0; nt < 4; nt++)
            bf[nt] = __ldg((const uint2*)&Wf[((ks * 16 + wn * 4 + nt) * 32 + lane) * 2]);
#pragma unroll
        for (int mt = 0; mt < 4; mt++)
#pragma unroll
            for (int nt = 0; nt < 4; nt++)
                mma_tf32(acc[mt][nt], (const uint32_t*)&af[mt], (const uint32_t*)&bf[nt]);
    }

    int g = lane >> 2, t4 = lane & 3;
#pragma unroll
    for (int mt = 0; mt < 4; mt++) {
        int rl = wm * 64 + mt * 16 + g;
        int t0 = sI1[rl], t1 = sI1[rl + 8];
#pragma unroll
        for (int nt = 0; nt < 4; nt++) {
            int cc = wn * 32 + nt * 8 + t4 * 2;
            float b0 = sB[cc], b1 = sB[cc + 1];
            red2(&g_agg[(size_t)t0 * 128 + cc], acc[mt][nt][0] + b0, acc[mt][nt][1] + b1);
            red2(&g_agg[(size_t)t1 * 128 + cc], acc[mt][nt][2] + b0, acc[mt][nt][3] + b1);
        }
    }
}

// ---------------- node-level mma kernels (391 CTAs, tail-guarded) ----------------

__global__ void __launch_bounds__(256, 2)
gemm_n2l1(const float* __restrict__ bias) {
    constexpr int KS2 = 22;  // K = 176
    extern __shared__ __align__(16) uint32_t A2[];
    __shared__ float xcs[128], xcq[128];
    __shared__ float sInv[128], sB[128];

    int tid = threadIdx.x;
    int lane = tid & 31, w = tid >> 5;
    int wm = w >> 2, wn = w & 3;
    int rbase = blockIdx.x * 128;

    if (tid < 128) {
        int r = rbase + tid;
        xcs[tid] = 0.f;
        xcq[tid] = 0.f;
        sB[tid] = bias[tid];
        sInv[tid] = (r < NN) ? 1.f / fmaxf((float)g_colcnt[r], 1.f) : 0.f;
    }
    __syncthreads();

    for (int v = tid; v < 128 * 44; v += 256) {
        int r = v / 44, q = v % 44;
        int gr = rbase + r;
        float4 val = make_float4(0.f, 0.f, 0.f, 0.f);
        if (gr < NN) {
            if (q < 12) {
                val = *(const float4*)(g_xbn + (size_t)gr * 48 + q * 4);
            } else {
                float4 a = ((const float4*)(g_agg + (size_t)gr * 128))[q - 12];
                float iv = sInv[r];
                val.x = a.x * iv; val.y = a.y * iv; val.z = a.z * iv; val.w = a.w * iv;
            }
        }
        int base = a2idx(KS2, r, q >> 1, (q & 1) * 4);
        A2[base + 0] = to_tf32(val.x);
        A2[base + 4] = to_tf32(val.y);
        A2[base + 8] = to_tf32(val.z);
        A2[base + 12] = to_tf32(val.w);
    }
    __syncthreads();

    float acc[4][4][4];
#pragma unroll
    for (int mt = 0; mt < 4; mt++)
#pragma unroll
        for (int nt = 0; nt < 4; nt++)
#pragma unroll
            for (int e = 0; e < 4; e++) acc[mt][nt][e] = 0.f;

    const uint32_t* Wf = g_wfrag + 67584;  // n2W1
#pragma unroll 2
    for (int ks = 0; ks < KS2; ks++) {
        uint4 af[4];
        uint2 bf[4];
#pragma unroll
        for (int mt = 0; mt < 4; mt++)
            af[mt] = *(const uint4*)&A2[(((wm * 4 + mt) * KS2 + ks) * 32 + lane) * 4];
#pragma unroll
        for (int nt = 0; nt < 4; nt++)
            bf[nt] = __ldg((const uint2*)&Wf[((ks * 16 + wn * 4 + nt) * 32 + lane) * 2]);
#pragma unroll
        for (int mt = 0; mt < 4; mt++)
#pragma unroll
            for (int nt = 0; nt < 4; nt++)
                mma_tf32(acc[mt][nt], (const uint32_t*)&af[mt], (const uint32_t*)&bf[nt]);
    }

    int g = lane >> 2, t4 = lane & 3;
#pragma unroll
    for (int nt = 0; nt < 4; nt++) {
        int cc = wn * 32 + nt * 8 + t4 * 2;
        float b0 = sB[cc], b1 = sB[cc + 1];
        float s0 = 0.f, q0 = 0.f, s1 = 0.f, q1 = 0.f;
#pragma unroll
        for (int mt = 0; mt < 4; mt++) {
            int gr = rbase + wm * 64 + mt * 16 + g;
            float v0 = acc[mt][nt][0] + b0, v1 = acc[mt][nt][1] + b1;
            float v2 = acc[mt][nt][2] + b0, v3 = acc[mt][nt][3] + b1;
            if (gr < NN) {
                *(float2*)(g_h3 + (size_t)gr * 128 + cc) = make_float2(v0, v1);
                s0 += v0; q0 += v0 * v0; s1 += v1; q1 += v1 * v1;
            }
            if (gr + 8 < NN) {
                *(float2*)(g_h3 + (size_t)(gr + 8) * 128 + cc) = make_float2(v2, v3);
                s0 += v2; q0 += v2 * v2; s1 += v3; q1 += v3 * v3;
            }
        }
        atomicAdd(&xcs[cc], s0);
        atomicAdd(&xcq[cc], q0);
        atomicAdd(&xcs[cc + 1], s1);
        atomicAdd(&xcq[cc + 1], q1);
    }
    __syncthreads();
    if (tid < 128) {
        atomicAdd(&g_stat[608 + tid], xcs[tid]);
        atomicAdd(&g_stat[736 + tid], xcq[tid]);
    }
}

__global__ void __launch_bounds__(256, 2)
gemm_n2l2(const float* __restrict__ bias, const int* __restrict__ batch) {
    constexpr int KS = 16;
    extern __shared__ __align__(16) uint32_t A2[];
    __shared__ int sI1[128];
    __shared__ float sSc[128], sSh[128], sB[128];

    int tid = threadIdx.x;
    int lane = tid & 31, w = tid >> 5;
    int wm = w >> 2, wn = w & 3;
    int rbase = blockIdx.x * 128;

    if (tid < 128) {
        int r = rbase + tid;
        sB[tid] = bias[tid];
        sI1[tid] = (r < NN) ? clampi(batch[r], GG) : 0;
        sSc[tid] = g_ss[608 + tid];
        sSh[tid] = g_ss[736 + tid];
    }
    __syncthreads();

    for (int v = tid; v < 128 * 32; v += 256) {
        int r = v >> 5, q = v & 31;
        int gr = rbase + r;
        float4 val = make_float4(0.f, 0.f, 0.f, 0.f);
        if (gr < NN) {
            float4 h = ((const float4*)(g_h3 + (size_t)gr * 128))[q];
            int c = q * 4;
            val.x = fmaxf(h.x * sSc[c + 0] + sSh[c + 0], 0.f);
            val.y = fmaxf(h.y * sSc[c + 1] + sSh[c + 1], 0.f);
            val.z = fmaxf(h.z * sSc[c + 2] + sSh[c + 2], 0.f);
            val.w = fmaxf(h.w * sSc[c + 3] + sSh[c + 3], 0.f);
        }
        int base = a2idx(KS, r, q >> 1, (q & 1) * 4);
        A2[base + 0] = to_tf32(val.x);
        A2[base + 4] = to_tf32(val.y);
        A2[base + 8] = to_tf32(val.z);
        A2[base + 12] = to_tf32(val.w);
    }
    __syncthreads();

    float acc[4][4][4];
#pragma unroll
    for (int mt = 0; mt < 4; mt++)
#pragma unroll
        for (int nt = 0; nt < 4; nt++)
#pragma unroll
            for (int e = 0; e < 4; e++) acc[mt][nt][e] = 0.f;

    const uint32_t* Wf = g_wfrag + 90112;  // n2W2
#pragma unroll 4
    for (int ks = 0; ks < KS; ks++) {
        uint4 af[4];
        uint2 bf[4];
#pragma unroll
        for (int mt = 0; mt < 4; mt++)
            af[mt] = *(const uint4*)&A2[(((wm * 4 + mt) * KS + ks) * 32 + lane) * 4];
#pragma unroll
        for (int nt = 0; nt < 4; nt++)
            bf[nt] = __ldg((const uint2*)&Wf[((ks * 16 + wn * 4 + nt) * 32 + lane) * 2]);
#pragma unroll
        for (int mt = 0; mt < 4; mt++)
#pragma unroll
            for (int nt = 0; nt < 4; nt++)
                mma_tf32(acc[mt][nt], (const uint32_t*)&af[mt], (const uint32_t*)&bf[nt]);
    }

    int g = lane >> 2, t4 = lane & 3;
#pragma unroll
    for (int mt = 0; mt < 4; mt++) {
        int rl = wm * 64 + mt * 16 + g;
        int gr0 = rbase + rl, gr1 = gr0 + 8;
        int t0 = sI1[rl], t1 = sI1[rl + 8];
#pragma unroll
        for (int nt = 0; nt < 4; nt++) {
            int cc = wn * 32 + nt * 8 + t4 * 2;
            float b0 = sB[cc], b1 = sB[cc + 1];
            if (gr0 < NN) red2(&g_usum[(size_t)t0 * 128 + cc], acc[mt][nt][0] + b0, acc[mt][nt][1] + b1);
            if (gr1 < NN) red2(&g_usum[(size_t)t1 * 128 + cc], acc[mt][nt][2] + b0, acc[mt][nt][3] + b1);
        }
    }
}

// ---------------- FFMA2 SGEMM for the tiny global layer ----------------
#define KC 32
#define LDT 132

__global__ void __launch_bounds__(256, 2)
gemm_gl1(const float* __restrict__ W, const float* __restrict__ bias) {
    __shared__ __align__(16) float Ast[KC * LDT];
    __shared__ __align__(16) float Ws[KC * 128];
    __shared__ float xcs[128], xcq[128];
    __shared__ float sInv[128];

    int tid = threadIdx.x;
    int tx = tid & 15, ty = tid >> 4;
    int rbase = blockIdx.x * 128;

    if (tid < 128) {
        int r = rbase + tid;
        xcs[tid] = 0.f;
        xcq[tid] = 0.f;
        sInv[tid] = (r < GG) ? 1.f / fmaxf((float)g_gcnt[r], 1.f) : 0.f;
    }
    __syncthreads();

    u64 accp[4][8];
#pragma unroll
    for (int p = 0; p < 4; p++)
#pragma unroll
        for (int j = 0; j < 8; j++) accp[p][j] = 0ull;

#pragma unroll
    for (int kb = 0; kb < 128; kb += KC) {
        for (int v = tid; v < KC * 32; v += 256)
            ((float4*)Ws)[v] = ((const float4*)(W + (size_t)kb * 128))[v];

        for (int v = tid; v < 128 * 8; v += 256) {
            int r = v / 8, ql = v % 8;
            int q = kb / 4 + ql;
            int gr = rbase + r;
            float4 val = make_float4(0.f, 0.f, 0.f, 0.f);
            if (gr < GG) {
                float4 a = ((const float4*)(g_usum + (size_t)gr * 128))[q];
                float iv = sInv[r];
                val.x = a.x * iv; val.y = a.y * iv; val.z = a.z * iv; val.w = a.w * iv;
            }
            int kl = ql * 4;
            Ast[(kl + 0) * LDT + r] = val.x;
            Ast[(kl + 1) * LDT + r] = val.y;
            Ast[(kl + 2) * LDT + r] = val.z;
            Ast[(kl + 3) * LDT + r] = val.w;
        }
        __syncthreads();

        const float* Wp = Ws + tx * 8;
        const float* Ap = Ast + ty * 8;
#pragma unroll
        for (int k = 0; k < KC; k++) {
            float4 b0 = *(const float4*)(Wp + k * 128);
            float4 b1 = *(const float4*)(Wp + k * 128 + 4);
            u64 bd[8];
            bd[0] = pack2(b0.x, b0.x); bd[1] = pack2(b0.y, b0.y);
            bd[2] = pack2(b0.z, b0.z); bd[3] = pack2(b0.w, b0.w);
            bd[4] = pack2(b1.x, b1.x); bd[5] = pack2(b1.y, b1.y);
            bd[6] = pack2(b1.z, b1.z); bd[7] = pack2(b1.w, b1.w);
            ulonglong2 aA = *(const ulonglong2*)(Ap + k * LDT);
            ulonglong2 aB = *(const ulonglong2*)(Ap + k * LDT + 4);
            u64 ap[4] = {aA.x, aA.y, aB.x, aB.y};
#pragma unroll
            for (int p = 0; p < 4; p++)
#pragma unroll
                for (int j = 0; j < 8; j++) ffma2(accp[p][j], ap[p], bd[j]);
        }
        __syncthreads();
    }

    float acc[8][8];
#pragma unroll
    for (int p = 0; p < 4; p++)
#pragma unroll
        for (int j = 0; j < 8; j++)
            unpack2(accp[p][j], acc[2 * p][j], acc[2 * p + 1][j]);

    int cb = tx * 8;
    float bs[8];
#pragma unroll
    for (int j = 0; j < 8; j++) bs[j] = bias[cb + j];
#pragma unroll
    for (int i = 0; i < 8; i++)
#pragma unroll
        for (int j = 0; j < 8; j++) acc[i][j] += bs[j];

    float s[8], q[8];
#pragma unroll
    for (int j = 0; j < 8; j++) { s[j] = 0.f; q[j] = 0.f; }
#pragma unroll
    for (int i = 0; i < 8; i++) {
        int gr = rbase + ty * 8 + i;
        if (gr < GG) {
            *(float4*)(g_hg + (size_t)gr * 128 + cb) = make_float4(acc[i][0], acc[i][1], acc[i][2], acc[i][3]);
            *(float4*)(g_hg + (size_t)gr * 128 + cb + 4) = make_float4(acc[i][4], acc[i][5], acc[i][6], acc[i][7]);
#pragma unroll
            for (int j = 0; j < 8; j++) {
                s[j] += acc[i][j];
                q[j] += acc[i][j] * acc[i][j];
            }
        }
    }
#pragma unroll
    for (int j = 0; j < 8; j++) {
        atomicAdd(&xcs[cb + j], s[j]);
        atomicAdd(&xcq[cb + j], q[j]);
    }
    __syncthreads();
    if (tid < 128) {
        atomicAdd(&g_stat[864 + tid], xcs[tid]);
        atomicAdd(&g_stat[992 + tid], xcq[tid]);
    }
}

__global__ void glout_k(const float* __restrict__ W2, const float* __restrict__ b2,
                        float* __restrict__ out) {
    int g = threadIdx.x;
    float a0 = 0.f, a1 = 0.f;
    for (int c = 0; c < 128; c++) {
        float h = fmaxf(g_hg[g * 128 + c] * g_ss[864 + c] + g_ss[992 + c], 0.f);
        a0 = fmaf(h, W2[c * 2 + 0], a0);
        a1 = fmaf(h, W2[c * 2 + 1], a1);
    }
    out[g * 2 + 0] = a0 + b2[0];
    out[g * 2 + 1] = a1 + b2[1];
}

// ---------------- host ----------------
extern "C" void kernel_launch(void* const* d_in, const int* in_sizes, int n_in,
                              void* d_out, int out_size) {
    (void)in_sizes; (void)n_in; (void)out_size;
    const float* x = (const float*)d_in[0];
    const int* ei = (const int*)d_in[1];
    const int* batch = (const int*)d_in[2];
    const float* bn_g = (const float*)d_in[3];
    const float* bn_b = (const float*)d_in[4];
    const float* eW1 = (const float*)d_in[5];
    const float* eb1 = (const float*)d_in[6];
    const float* eg = (const float*)d_in[7];
    const float* ebe = (const float*)d_in[8];
    const float* eW2 = (const float*)d_in[9];
    const float* eb2 = (const float*)d_in[10];
    const float* n1W1 = (const float*)d_in[11];
    const float* n1b1 = (const float*)d_in[12];
    const float* n1g = (const float*)d_in[13];
    const float* n1be = (const float*)d_in[14];
    const float* n1W2 = (const float*)d_in[15];
    const float* n1b2 = (const float*)d_in[16];
    const float* n2W1 = (const float*)d_in[17];
    const float* n2b1 = (const float*)d_in[18];
    const float* n2g = (const float*)d_in[19];
    const float* n2be = (const float*)d_in[20];
    const float* n2W2 = (const float*)d_in[21];
    const float* n2b2 = (const float*)d_in[22];
    const float* glW1 = (const float*)d_in[23];
    const float* glb1 = (const float*)d_in[24];
    const float* glg = (const float*)d_in[25];
    const float* glbe = (const float*)d_in[26];
    const float* glW2 = (const float*)d_in[27];
    const float* glb2 = (const float*)d_in[28];

    const int* row = ei;
    const int* col = ei + EE;

    const int EB = EE / 128;          // 12500
    const int NB = (NN + 127) / 128;  // 391

    const int SM_E1 = 12 * 4096;      // 49152
    const int SM_FUSE = 26624 * 4;    // 106496
    const int SM_N1L2 = 16 * 4096;    // 65536
    const int SM_N2L1 = 22 * 4096;    // 90112
    cudaFuncSetAttribute(gemm_e1, cudaFuncAttributeMaxDynamicSharedMemorySize, SM_E1);
    cudaFuncSetAttribute(gemm_fuse, cudaFuncAttributeMaxDynamicSharedMemorySize, SM_FUSE);
    cudaFuncSetAttribute(gemm_n1l2, cudaFuncAttributeMaxDynamicSharedMemorySize, SM_N1L2);
    cudaFuncSetAttribute(gemm_n2l1, cudaFuncAttributeMaxDynamicSharedMemorySize, SM_N2L1);
    cudaFuncSetAttribute(gemm_n2l2, cudaFuncAttributeMaxDynamicSharedMemorySize, SM_N1L2);

    zero_k<<<2048, 256>>>();
    xstats_k<<<512, 256>>>(x);
    finalize_k<<<1, 48>>>(bn_g, bn_b, 0, 0, 48, 48, (float)NN);
    xbn_k<<<2048, 256>>>(x);
    count_k<<<2048, 256>>>(col, batch);
    prep_all<<<148, 256>>>(eW1, eW2, n1W1, n1W2, n2W1, n2W2);

    gemm_e1<<<EB, 256, SM_E1>>>(eb1, row, col);
    finalize_k<<<1, 128>>>(eg, ebe, 96, 96, 224, 128, (float)EE);
    gemm_fuse<<<EB, 256, SM_FUSE>>>(eb2, n1b1, row);
    finalize_k<<<1, 128>>>(n1g, n1be, 352, 352, 480, 128, (float)EE);
    gemm_n1l2<<<EB, 256, SM_N1L2>>>(n1b2, col);

    gemm_n2l1<<<NB, 256, SM_N2L1>>>(n2b1);
    finalize_k<<<1, 128>>>(n2g, n2be, 608, 608, 736, 128, (float)NN);
    gemm_n2l2<<<NB, 256, SM_N1L2>>>(n2b2, batch);
    gemm_gl1<<<2, 256>>>(glW1, glb1);
    finalize_k<<<1, 128>>>(glg, glbe, 864, 864, 992, 128, 256.f);
    glout_k<<<1, 256>>>(glW2, glb2, (float*)d_out);
}